// round 14
// baseline (speedup 1.0000x reference)
#include <cuda_runtime.h>
#include <math_constants.h>

// MAM dense: C[n,j] = max_k(x[n,k]*w[j,k]) + min_k(x[n,k]*w[j,k]) + bias[j]
// x: [2048, 512] f32, w: [256, 512] f32, bias: [256] f32, out: [2048, 256] f32
//
// R14: R11's fatter thread tile (2n x 4j: 0.75 loaded-floats/product vs 1.0
// for 2x2 -> l1tex wf/SM 57K -> 46K) on R12's double-buffered single-barrier
// skeleton (R11's loss traced to its single-buffer 2-barrier pipeline, not
// the tile shape). 512 CTAs (32n x 32j, 128 thr), 4v3 residency accepted.
// Inner k: LDS.64 (a, 2n) + LDS.128 (b, 4j) -> 8 FMUL + 16 FMNMX.

constexpr int IN_F  = 512;
constexpr int OUT_F = 256;
constexpr int NROWS = 2048;

constexpr int TN = 32;
constexpr int TJ = 32;
constexpr int KB = 32;
constexpr int NCH = IN_F / KB;                   // 16
constexpr int TILES_J = OUT_F / TJ;              // 8
constexpr int NTILES  = (NROWS / TN) * TILES_J;  // 512
constexpr int THREADS = 128;

constexpr int XLD = 34;  // xs[k][n] stride (even -> LDS.64 aligned; 2-way STS max)
constexpr int WLD = 36;  // ws[k][j] stride (mult of 4 -> LDS.128 aligned)

__global__ __launch_bounds__(THREADS, 4)
void mam_kernel(const float* __restrict__ x,
                const float* __restrict__ w,
                const float* __restrict__ bias,
                float* __restrict__ out)
{
    __shared__ __align__(16) float xs[2][KB][XLD];
    __shared__ __align__(16) float ws[2][KB][WLD];

    const int tid = threadIdx.x;
    const int tn  = tid >> 3;          // 0..15 -> n pair
    const int tj  = tid & 7;           // 0..7  -> j quad
    const int j0  = (blockIdx.x & (TILES_J - 1)) * TJ;
    const int n0  = (blockIdx.x / TILES_J) * TN;

    // Loader mapping (coalesced: 4 consecutive rows per warp quarter).
    const int lr  = tid >> 3;          // 0..15 (rows lr, lr+16)
    const int lkq = (tid & 7) * 4;     // k quad: 0,4,...,28

    const float* xb = &x[(n0 + lr) * IN_F + lkq];
    const float* wb = &w[(j0 + lr) * IN_F + lkq];

    float mx[2][4], mn[2][4];
#pragma unroll
    for (int i = 0; i < 2; i++)
#pragma unroll
        for (int jj = 0; jj < 4; jj++) {
            mx[i][jj] = -CUDART_INF_F;
            mn[i][jj] =  CUDART_INF_F;
        }

    // Prefetch chunk 0 and stage into buffer 0.
    float4 xv0 = *reinterpret_cast<const float4*>(xb);
    float4 xv1 = *reinterpret_cast<const float4*>(xb + 16 * IN_F);
    float4 wv0 = *reinterpret_cast<const float4*>(wb);
    float4 wv1 = *reinterpret_cast<const float4*>(wb + 16 * IN_F);

#define STAGE(BUF)                                                        \
    {                                                                     \
        xs[BUF][lkq + 0][lr]      = xv0.x; xs[BUF][lkq + 1][lr]      = xv0.y; \
        xs[BUF][lkq + 2][lr]      = xv0.z; xs[BUF][lkq + 3][lr]      = xv0.w; \
        xs[BUF][lkq + 0][lr + 16] = xv1.x; xs[BUF][lkq + 1][lr + 16] = xv1.y; \
        xs[BUF][lkq + 2][lr + 16] = xv1.z; xs[BUF][lkq + 3][lr + 16] = xv1.w; \
        ws[BUF][lkq + 0][lr]      = wv0.x; ws[BUF][lkq + 1][lr]      = wv0.y; \
        ws[BUF][lkq + 2][lr]      = wv0.z; ws[BUF][lkq + 3][lr]      = wv0.w; \
        ws[BUF][lkq + 0][lr + 16] = wv1.x; ws[BUF][lkq + 1][lr + 16] = wv1.y; \
        ws[BUF][lkq + 2][lr + 16] = wv1.z; ws[BUF][lkq + 3][lr + 16] = wv1.w; \
    }

    STAGE(0)
    __syncthreads();   // buffer 0 ready

    for (int c = 0; c < NCH; c++) {
        // LDG next chunk first (latency overlapped with compute below).
        const bool more = (c + 1) < NCH;
        if (more) {
            const int kn = (c + 1) * KB;
            xv0 = *reinterpret_cast<const float4*>(xb + kn);
            xv1 = *reinterpret_cast<const float4*>(xb + 16 * IN_F + kn);
            wv0 = *reinterpret_cast<const float4*>(wb + kn);
            wv1 = *reinterpret_cast<const float4*>(wb + 16 * IN_F + kn);
        }

        // Compute current buffer.
        const int cb = c & 1;
        const float* agp = &xs[cb][0][2 * tn];
        const float* bgp = &ws[cb][0][4 * tj];
#pragma unroll
        for (int k = 0; k < KB; k++) {
            const float2 a = *reinterpret_cast<const float2*>(agp + k * XLD);
            const float4 b = *reinterpret_cast<const float4*>(bgp + k * WLD);
            float p;
            p = a.x * b.x; mx[0][0] = fmaxf(mx[0][0], p); mn[0][0] = fminf(mn[0][0], p);
            p = a.x * b.y; mx[0][1] = fmaxf(mx[0][1], p); mn[0][1] = fminf(mn[0][1], p);
            p = a.x * b.z; mx[0][2] = fmaxf(mx[0][2], p); mn[0][2] = fminf(mn[0][2], p);
            p = a.x * b.w; mx[0][3] = fmaxf(mx[0][3], p); mn[0][3] = fminf(mn[0][3], p);
            p = a.y * b.x; mx[1][0] = fmaxf(mx[1][0], p); mn[1][0] = fminf(mn[1][0], p);
            p = a.y * b.y; mx[1][1] = fmaxf(mx[1][1], p); mn[1][1] = fminf(mn[1][1], p);
            p = a.y * b.z; mx[1][2] = fmaxf(mx[1][2], p); mn[1][2] = fminf(mn[1][2], p);
            p = a.y * b.w; mx[1][3] = fmaxf(mx[1][3], p); mn[1][3] = fminf(mn[1][3], p);
        }

        // Stage next chunk into the other buffer; one barrier gives both
        // orderings (compute-done before overwrite 2 chunks later, and
        // stores visible before next iteration's reads).
        if (more) {
            const int nb = (c + 1) & 1;
            if (nb) { STAGE(1) } else { STAGE(0) }
            __syncthreads();
        }
    }
#undef STAGE

    // Epilogue: C = max + min + bias (two STG.128).
    const int j = j0 + 4 * tj;
    const int n = n0 + 2 * tn;
    const float4 bz = *reinterpret_cast<const float4*>(&bias[j]);
#pragma unroll
    for (int i = 0; i < 2; i++) {
        float4 r;
        r.x = mx[i][0] + mn[i][0] + bz.x;
        r.y = mx[i][1] + mn[i][1] + bz.y;
        r.z = mx[i][2] + mn[i][2] + bz.z;
        r.w = mx[i][3] + mn[i][3] + bz.w;
        *reinterpret_cast<float4*>(&out[(n + i) * OUT_F + j]) = r;
    }
}

extern "C" void kernel_launch(void* const* d_in, const int* in_sizes, int n_in,
                              void* d_out, int out_size)
{
    const float* x    = (const float*)d_in[0];   // [2048, 512]
    const float* w    = (const float*)d_in[1];   // [256, 512]
    const float* bias = (const float*)d_in[2];   // [256]
    float* out        = (float*)d_out;           // [2048, 256]

    mam_kernel<<<NTILES, THREADS>>>(x, w, bias, out);
}